// round 7
// baseline (speedup 1.0000x reference)
#include <cuda_runtime.h>
#include <cuda_fp16.h>
#include <float.h>
#include <stdint.h>

#define NCODES   4096
#define CDIM     64
#define NTOK     65536
#define HW       4096
#define M_TILE   128
#define NQ       4
#define QCODES   1024          // codes per quarter (resident in smem)
#define NCH      8             // 128-code chunks per quarter
#define THREADS  256
#define SCALE    64.0f
#define ESQ_SCALE 4096.0f

#define B_STRIDE 144           // 64 halves + 16B pad -> conflict-free ldmatrix

// ---- main kernel smem ----
#define OFF_CB    0                       // 1024*144 = 147456
#define OFF_ZS    147456                  // 64*132*4 = 33792 (overlaid by sb0/si0/sb1 later)
#define OFF_SESQ  181248                  // 4096
#define OFF_RED   185344                  // 1024
#define MAIN_SMEM 186368
// overlays (after main loop):
#define OFF_SB0   147456                  // 8*128 f
#define OFF_SI0   151552                  // 8*128 i
#define OFF_SB1   155648                  // 8*128 f

#define CMB_SMEM  34304                   // st[128*65]f + sidx[128]i

__device__ float  g_esq[NCODES];
__device__ __half g_embh[NCODES * CDIM];
__device__ float  g_wb0[NQ * NTOK];
__device__ float  g_wb1[NQ * NTOK];
__device__ int    g_wi0[NQ * NTOK];
__device__ float  g_zsq[NTOK];
__device__ int    g_emaxb;
__device__ int    g_fbcnt;
__device__ int    g_fblist[NTOK];

__device__ __forceinline__ uint32_t smem_u32(const void* p) {
    uint32_t a;
    asm("{ .reg .u64 t; cvta.to.shared.u64 t, %1; cvt.u32.u64 %0, t; }" : "=r"(a) : "l"(p));
    return a;
}
__device__ __forceinline__ void mma16816(float* c, const uint32_t* a, uint32_t b0, uint32_t b1) {
    asm volatile(
        "mma.sync.aligned.m16n8k16.row.col.f32.f16.f16.f32 "
        "{%0,%1,%2,%3}, {%4,%5,%6,%7}, {%8,%9}, {%0,%1,%2,%3};"
        : "+f"(c[0]), "+f"(c[1]), "+f"(c[2]), "+f"(c[3])
        : "r"(a[0]), "r"(a[1]), "r"(a[2]), "r"(a[3]), "r"(b0), "r"(b1));
}
__device__ __forceinline__ void ldmx4(uint32_t& r0, uint32_t& r1, uint32_t& r2, uint32_t& r3,
                                      uint32_t a) {
    asm volatile("ldmatrix.sync.aligned.m8n8.x4.shared.b16 {%0,%1,%2,%3}, [%4];"
        : "=r"(r0), "=r"(r1), "=r"(r2), "=r"(r3) : "r"(a));
}
__device__ __forceinline__ uint32_t pack2h(float v0, float v1) {
    __half h0 = __float2half_rn(v0);
    __half h1 = __float2half_rn(v1);
    return (uint32_t)__half_as_ushort(h0) | ((uint32_t)__half_as_ushort(h1) << 16);
}

// ---- init: reset per-replay accumulators ----
__global__ void init_kernel() {
    g_emaxb = 0;
    g_fbcnt = 0;
}

// ---- prep: esq, fp16 codebook (scaled), emax via atomicMax ----
__global__ void prep_kernel(const float* __restrict__ emb) {
    int warp = (blockIdx.x * blockDim.x + threadIdx.x) >> 5;
    int lane = threadIdx.x & 31;
    if (warp >= NCODES) return;
    const float* row = emb + (size_t)warp * CDIM;
    float v0 = row[lane], v1 = row[lane + 32];
    g_embh[warp * CDIM + lane]      = __float2half_rn(v0 * SCALE);
    g_embh[warp * CDIM + lane + 32] = __float2half_rn(v1 * SCALE);
    float s = v0 * v0 + v1 * v1;
    #pragma unroll
    for (int off = 16; off; off >>= 1) s += __shfl_xor_sync(0xffffffffu, s, off);
    if (lane == 0) {
        g_esq[warp] = s;
        atomicMax(&g_emaxb, __float_as_int(s));   // all esq > 0 -> int-ordered
    }
}

// ---- main: one (token-tile, code-quarter) per CTA; barrier-free MMA sweep ----
__global__ __launch_bounds__(THREADS, 1)
void vq_main(const float* __restrict__ z) {
    extern __shared__ char sm[];
    float* zs   = (float*)(sm + OFF_ZS);
    float* sesq = (float*)(sm + OFF_SESQ);
    float* red  = (float*)(sm + OFF_RED);
    float* sb0  = (float*)(sm + OFF_SB0);
    int*   si0  = (int*)(sm + OFF_SI0);
    float* sb1  = (float*)(sm + OFF_SB1);

    const int tid  = threadIdx.x;
    const int lane = tid & 31;
    const int wid  = tid >> 5;
    const int grp  = lane >> 2;
    const int tid4 = lane & 3;
    const int mwarp = wid >> 1;
    const int nw    = wid & 1;

    const int tile = blockIdx.x >> 2;
    const int q    = blockIdx.x & 3;
    const int n0   = tile * M_TILE;
    const int bb   = n0 >> 12;
    const int hw0  = n0 & (HW - 1);
    const float* zb = z + (size_t)bb * CDIM * HW + hw0;

    // load codebook quarter (fp16, scaled) into resident smem
    {
        const uint4* eh4 = (const uint4*)g_embh;
        for (int i = tid; i < QCODES * 8; i += THREADS) {
            int row = i >> 3, part = i & 7;
            uint4 v = __ldg(&eh4[(size_t)(q * QCODES + row) * 8 + part]);
            *(uint4*)(sm + OFF_CB + row * B_STRIDE + part * 16) = v;
        }
    }
    // stage z (scaled) + zsq partials
    {
        const int tok  = tid & 127;
        const int half = tid >> 7;
        float zp = 0.f;
        #pragma unroll
        for (int j = 0; j < 32; j++) {
            int c = half * 32 + j;
            float v = zb[(size_t)c * HW + tok] * SCALE;
            zs[c * 132 + tok] = v;
            zp = fmaf(v, v, zp);
        }
        red[tid] = zp;
    }
    // esq quarter (scaled)
    #pragma unroll
    for (int j = 0; j < 4; j++)
        sesq[tid + j * 256] = g_esq[q * QCODES + tid + j * 256] * ESQ_SCALE;
    __syncthreads();
    if (q == 0 && tid < 128) g_zsq[n0 + tid] = red[tid] + red[tid + 128];

    // A fragments in registers
    uint32_t Ah[2][4][4];
    #pragma unroll
    for (int m = 0; m < 2; m++) {
        int r0 = mwarp * 32 + m * 16 + grp;
        #pragma unroll
        for (int s = 0; s < 4; s++) {
            int kb = 2 * tid4 + 16 * s;
            Ah[m][s][0] = pack2h(zs[kb * 132 + r0],           zs[(kb + 1) * 132 + r0]);
            Ah[m][s][1] = pack2h(zs[kb * 132 + r0 + 8],       zs[(kb + 1) * 132 + r0 + 8]);
            Ah[m][s][2] = pack2h(zs[(kb + 8) * 132 + r0],     zs[(kb + 9) * 132 + r0]);
            Ah[m][s][3] = pack2h(zs[(kb + 8) * 132 + r0 + 8], zs[(kb + 9) * 132 + r0 + 8]);
        }
    }
    __syncthreads();   // zs free for overlay after this; CB fully written

    const int lrow  = (lane & 7) + ((lane >> 4) & 1) * 8;
    const int lkoff = ((lane >> 3) & 1) * 16;
    const uint32_t cb_u32 = smem_u32(sm + OFF_CB);

    float b0v[4], b1v[4];
    int   b0i[4];
    #pragma unroll
    for (int g = 0; g < 4; g++) { b0v[g] = FLT_MAX; b1v[g] = FLT_MAX; b0i[g] = 0; }

    // ---- barrier-free main loop over 8 resident 128-code chunks ----
    #pragma unroll 1
    for (int ch = 0; ch < NCH; ch++) {
        const int lcb = ch * 128 + nw * 64;   // local code base for this warp
        const uint32_t bbuf = cb_u32 + (uint32_t)(lcb + lrow) * B_STRIDE + lkoff;

        float acc[2][8][4];
        #pragma unroll
        for (int m = 0; m < 2; m++)
            #pragma unroll
            for (int f = 0; f < 8; f++)
                #pragma unroll
                for (int r = 0; r < 4; r++) acc[m][f][r] = 0.f;

        #pragma unroll
        for (int s = 0; s < 4; s++) {
            #pragma unroll
            for (int fp = 0; fp < 4; fp++) {
                uint32_t h0, h1, h2, h3;
                ldmx4(h0, h1, h2, h3, bbuf + fp * (16 * B_STRIDE) + s * 32);
                mma16816(acc[0][2 * fp],     Ah[0][s], h0, h1);
                mma16816(acc[1][2 * fp],     Ah[1][s], h0, h1);
                mma16816(acc[0][2 * fp + 1], Ah[0][s], h2, h3);
                mma16816(acc[1][2 * fp + 1], Ah[1][s], h2, h3);
            }
        }

        float2 ee[8];
        #pragma unroll
        for (int f = 0; f < 8; f++)
            ee[f] = *(const float2*)&sesq[lcb + f * 8 + 2 * tid4];

        #pragma unroll
        for (int m = 0; m < 2; m++) {
            #pragma unroll
            for (int h = 0; h < 2; h++) {
                const int g = m * 2 + h;
                float sv[16];
                #pragma unroll
                for (int f = 0; f < 8; f++) {
                    sv[2 * f]     = fmaf(acc[m][f][h * 2 + 0], -2.0f, ee[f].x);
                    sv[2 * f + 1] = fmaf(acc[m][f][h * 2 + 1], -2.0f, ee[f].y);
                }
                float mn = sv[0];
                #pragma unroll
                for (int j = 1; j < 16; j++) mn = fminf(mn, sv[j]);
                if (mn < b1v[g]) {
                    #pragma unroll
                    for (int j = 0; j < 16; j++) {
                        float v = sv[j];
                        if (v < b0v[g]) {
                            b1v[g] = b0v[g];
                            b0v[g] = v;
                            b0i[g] = q * QCODES + lcb + (j >> 1) * 8 + 2 * tid4 + (j & 1);
                        } else if (v < b1v[g]) {
                            b1v[g] = v;
                        }
                    }
                }
            }
        }
    }

    // ---- dump slots, merge to exact per-quarter top-2, write workspace ----
    {
        const int slot = nw * 4 + tid4;
        #pragma unroll
        for (int g = 0; g < 4; g++) {
            int token = mwarp * 32 + (g >> 1) * 16 + (g & 1) * 8 + grp;
            sb0[slot * 128 + token] = b0v[g];
            si0[slot * 128 + token] = b0i[g];
            sb1[slot * 128 + token] = b1v[g];
        }
    }
    __syncthreads();
    if (tid < 128) {
        const int t = tid;
        float v0 = FLT_MAX, v1 = FLT_MAX, w1 = FLT_MAX;
        int i0 = 0;
        #pragma unroll
        for (int s = 0; s < 8; s++) {
            float bv = sb0[s * 128 + t];
            int   bi = si0[s * 128 + t];
            float b1s = sb1[s * 128 + t];
            if (bv < v0 || (bv == v0 && bi < i0)) {
                v1 = fminf(v1, v0);
                v0 = bv; i0 = bi; w1 = b1s;
            } else {
                v1 = fminf(v1, bv);
            }
        }
        v1 = fminf(v1, w1);
        const int wsi = q * NTOK + n0 + t;
        g_wb0[wsi] = v0;
        g_wi0[wsi] = i0;
        g_wb1[wsi] = v1;
    }
}

// ---- combine: merge quarters, verify threshold, rescore candidates, gather ----
__global__ __launch_bounds__(128, 8)
void vq_combine(const float* __restrict__ z,
                const float* __restrict__ emb,
                float* __restrict__ out) {
    extern __shared__ char sm[];
    float* st   = (float*)sm;             // [128][65]
    int*   sidx = (int*)(sm + 33280);     // [128]

    const int tid  = threadIdx.x;
    const int tile = blockIdx.x;
    const int n0   = tile * M_TILE;
    const int bb   = n0 >> 12;
    const int hw0  = n0 & (HW - 1);
    const float emax2 = __int_as_float(g_emaxb) * ESQ_SCALE;

    {
        const int t = tid;
        const int gtok = n0 + t;
        float qb0[4], qb1[4];
        int   qi0[4];
        #pragma unroll
        for (int q = 0; q < 4; q++) {
            qb0[q] = g_wb0[q * NTOK + gtok];
            qb1[q] = g_wb1[q * NTOK + gtok];
            qi0[q] = g_wi0[q * NTOK + gtok];
        }
        float gv = qb0[0]; int gi = qi0[0];
        #pragma unroll
        for (int q = 1; q < 4; q++)
            if (qb0[q] < gv || (qb0[q] == gv && qi0[q] < gi)) { gv = qb0[q]; gi = qi0[q]; }

        const float thr = gv + 0.0041f * sqrtf(g_zsq[gtok] * emax2) + 32.0f;
        bool fb = false;
        int cand[4], nc = 0;
        #pragma unroll
        for (int q = 0; q < 4; q++) {
            if (qb1[q] <= thr) fb = true;
            if (qb0[q] <= thr) cand[nc++] = qi0[q];
        }
        int best = gi;
        if (!fb && nc > 1) {
            const float* zt = z + (size_t)bb * CDIM * HW + hw0 + t;
            float zloc[64];
            #pragma unroll
            for (int c = 0; c < 64; c++) zloc[c] = zt[(size_t)c * HW];
            float bd = FLT_MAX; int bi = 0;
            for (int j = 0; j < nc; j++) {
                int cd = cand[j];
                const float4* e4 = (const float4*)(emb + (size_t)cd * CDIM);
                float dot = 0.f;
                #pragma unroll
                for (int k4 = 0; k4 < 16; k4++) {
                    float4 e = __ldg(&e4[k4]);
                    dot = fmaf(zloc[4 * k4 + 0], e.x, dot);
                    dot = fmaf(zloc[4 * k4 + 1], e.y, dot);
                    dot = fmaf(zloc[4 * k4 + 2], e.z, dot);
                    dot = fmaf(zloc[4 * k4 + 3], e.w, dot);
                }
                float d = g_esq[cd] - 2.0f * dot;
                if (d < bd || (d == bd && cd < bi)) { bd = d; bi = cd; }
            }
            best = bi;
        }
        if (fb) {
            int p = atomicAdd(&g_fbcnt, 1);
            g_fblist[p] = gtok;
        }
        sidx[t] = best;   // provisional for fb tokens; fallback kernel overwrites output
    }
    __syncthreads();

    // gather + transposed coalesced write
    for (int i = tid; i < M_TILE * CDIM; i += 128) {
        int tok = i >> 6, c = i & 63;
        st[tok * 65 + c] = emb[(size_t)sidx[tok] * CDIM + c];
    }
    __syncthreads();
    float* ob = out + (size_t)bb * CDIM * HW + hw0;
    for (int i = tid; i < CDIM * M_TILE; i += 128) {
        int c = i >> 7, tok = i & (M_TILE - 1);
        ob[(size_t)c * HW + tok] = st[tok * 65 + c];
    }
}

// ---- fallback: exact fp32 rescan for flagged tokens ----
__global__ __launch_bounds__(256, 4)
void vq_fallback(const float* __restrict__ z,
                 const float* __restrict__ emb,
                 float* __restrict__ out) {
    __shared__ float zloc[64];
    __shared__ float rv[8];
    __shared__ int   ri[8];
    __shared__ int   bestc;

    if (blockIdx.x >= g_fbcnt) return;
    const int gtok = g_fblist[blockIdx.x];
    const int tid  = threadIdx.x;
    const int lane = tid & 31;
    const int wid  = tid >> 5;
    const int bb   = gtok >> 12;
    const int hw   = gtok & (HW - 1);
    const float* zt = z + (size_t)bb * CDIM * HW + hw;

    if (tid < 64) zloc[tid] = zt[(size_t)tid * HW];
    __syncthreads();

    float bv = FLT_MAX; int bi = 0;
    for (int c = tid; c < NCODES; c += 256) {
        const float4* e4 = (const float4*)(emb + (size_t)c * CDIM);
        float dot = 0.f;
        #pragma unroll
        for (int k4 = 0; k4 < 16; k4++) {
            float4 e = __ldg(&e4[k4]);
            dot = fmaf(zloc[4 * k4 + 0], e.x, dot);
            dot = fmaf(zloc[4 * k4 + 1], e.y, dot);
            dot = fmaf(zloc[4 * k4 + 2], e.z, dot);
            dot = fmaf(zloc[4 * k4 + 3], e.w, dot);
        }
        float d = g_esq[c] - 2.0f * dot;
        if (d < bv || (d == bv && c < bi)) { bv = d; bi = c; }
    }
    #pragma unroll
    for (int off = 16; off; off >>= 1) {
        float ov = __shfl_xor_sync(0xffffffffu, bv, off);
        int   oi = __shfl_xor_sync(0xffffffffu, bi, off);
        if (ov < bv || (ov == bv && oi < bi)) { bv = ov; bi = oi; }
    }
    if (lane == 0) { rv[wid] = bv; ri[wid] = bi; }
    __syncthreads();
    if (tid == 0) {
        float fv = rv[0]; int fi = ri[0];
        #pragma unroll
        for (int w = 1; w < 8; w++)
            if (rv[w] < fv || (rv[w] == fv && ri[w] < fi)) { fv = rv[w]; fi = ri[w]; }
        bestc = fi;
    }
    __syncthreads();
    if (tid < 64)
        out[(size_t)bb * CDIM * HW + (size_t)tid * HW + hw] = emb[(size_t)bestc * CDIM + tid];
}

extern "C" void kernel_launch(void* const* d_in, const int* in_sizes, int n_in,
                              void* d_out, int out_size) {
    const float* z   = (const float*)d_in[0];
    const float* emb = (const float*)d_in[1];
    float* out = (float*)d_out;

    cudaFuncSetAttribute(vq_main, cudaFuncAttributeMaxDynamicSharedMemorySize, MAIN_SMEM);
    cudaFuncSetAttribute(vq_combine, cudaFuncAttributeMaxDynamicSharedMemorySize, CMB_SMEM);

    init_kernel<<<1, 1>>>();
    prep_kernel<<<NCODES / 8, 256>>>(emb);
    vq_main<<<(NTOK / M_TILE) * NQ, THREADS, MAIN_SMEM>>>(z);
    vq_combine<<<NTOK / M_TILE, 128, CMB_SMEM>>>(z, emb, out);
    vq_fallback<<<2048, 256>>>(z, emb, out);
}

// round 8
// speedup vs baseline: 2.8193x; 2.8193x over previous
#include <cuda_runtime.h>
#include <cuda_fp16.h>
#include <float.h>
#include <stdint.h>

#define NCODES   4096
#define CDIM     64
#define NTOK     65536
#define HW       4096
#define M_TILE   64
#define N_CHUNK  128
#define NCHUNKS  32
#define THREADS  256
#define SCALE    64.0f
#define ESQ_SCALE 4096.0f

#define B_STRIDE 144   // 64 halves (128B) + 16B pad -> conflict-free ldmatrix

// ---- smem byte offsets (per CTA total 108800 -> 2 CTAs/SM) ----
#define OFF_ZS     0        // 64*68*4 = 17408 fp32 z (scaled); reused as gather stage
#define OFF_ESQ    17408    // 16384
#define OFF_BH0    33792    // 18432
#define OFF_BL0    52224    // 18432
#define OFF_BH1    70656    // 18432
#define OFF_BL1    89088    // 18432 (ends 107520)
#define OFF_CANDV  107520   // 2*64 floats = 512
#define OFF_CANDI  108032   // 512
#define OFF_SIDX   108544   // 256
#define SMEM_TOTAL 108800

__device__ float  g_esq[NCODES];             // scaled by 4096
__device__ __half g_embh[NCODES * CDIM];     // hi(e*64)
__device__ __half g_embl[NCODES * CDIM];     // lo(e*64)

__device__ __forceinline__ uint32_t smem_u32(const void* p) {
    uint32_t a;
    asm("{ .reg .u64 t; cvta.to.shared.u64 t, %1; cvt.u32.u64 %0, t; }" : "=r"(a) : "l"(p));
    return a;
}
__device__ __forceinline__ void cp16(uint32_t dst, const void* src) {
    asm volatile("cp.async.cg.shared.global [%0], [%1], 16;" :: "r"(dst), "l"(src));
}
__device__ __forceinline__ void cp_commit() { asm volatile("cp.async.commit_group;"); }
template <int N>
__device__ __forceinline__ void cp_wait() { asm volatile("cp.async.wait_group %0;" :: "n"(N)); }

__device__ __forceinline__ void mma16816(float* c, const uint32_t* a, uint32_t b0, uint32_t b1) {
    asm volatile(
        "mma.sync.aligned.m16n8k16.row.col.f32.f16.f16.f32 "
        "{%0,%1,%2,%3}, {%4,%5,%6,%7}, {%8,%9}, {%0,%1,%2,%3};"
        : "+f"(c[0]), "+f"(c[1]), "+f"(c[2]), "+f"(c[3])
        : "r"(a[0]), "r"(a[1]), "r"(a[2]), "r"(a[3]), "r"(b0), "r"(b1));
}
__device__ __forceinline__ void ldmx4(uint32_t& r0, uint32_t& r1, uint32_t& r2, uint32_t& r3,
                                      uint32_t a) {
    asm volatile("ldmatrix.sync.aligned.m8n8.x4.shared.b16 {%0,%1,%2,%3}, [%4];"
        : "=r"(r0), "=r"(r1), "=r"(r2), "=r"(r3) : "r"(a));
}
__device__ __forceinline__ uint32_t pack2h(float v0, float v1) {
    __half h0 = __float2half_rn(v0);
    __half h1 = __float2half_rn(v1);
    return (uint32_t)__half_as_ushort(h0) | ((uint32_t)__half_as_ushort(h1) << 16);
}

// prep: hi/lo fp16 codebook (scaled by 64) + scaled ||e||^2. one warp per code.
__global__ void prep_kernel(const float* __restrict__ emb) {
    int warp = (blockIdx.x * blockDim.x + threadIdx.x) >> 5;
    int lane = threadIdx.x & 31;
    if (warp >= NCODES) return;
    const float* row = emb + (size_t)warp * CDIM;
    float v0 = row[lane] * SCALE, v1 = row[lane + 32] * SCALE;
    __half h0 = __float2half_rn(v0), h1 = __float2half_rn(v1);
    g_embh[warp * CDIM + lane]      = h0;
    g_embh[warp * CDIM + lane + 32] = h1;
    g_embl[warp * CDIM + lane]      = __float2half_rn(v0 - __half2float(h0));
    g_embl[warp * CDIM + lane + 32] = __float2half_rn(v1 - __half2float(h1));
    float s = v0 * v0 + v1 * v1;   // already scale^2 * ||e||^2
    #pragma unroll
    for (int off = 16; off; off >>= 1) s += __shfl_xor_sync(0xffffffffu, s, off);
    if (lane == 0) g_esq[warp] = s;
}

__global__ __launch_bounds__(THREADS, 2)
void vq_kernel(const float* __restrict__ z,
               const float* __restrict__ emb,
               float* __restrict__ out) {
    extern __shared__ char sm[];
    float* zs    = (float*)(sm + OFF_ZS);     // [64][68]
    float* esq_s = (float*)(sm + OFF_ESQ);    // [4096]
    float* candv = (float*)(sm + OFF_CANDV);  // [2][64]
    int*   candi = (int*)(sm + OFF_CANDI);
    int*   sidx  = (int*)(sm + OFF_SIDX);     // [64]

    const uint32_t sb = smem_u32(sm);
    const int tid  = threadIdx.x;
    const int lane = tid & 31;
    const int wid  = tid >> 5;
    const int grp  = lane >> 2;     // 0..7
    const int tid4 = lane & 3;      // 0..3
    const int mwarp = wid >> 1;     // 0..3 : token rows mwarp*16 + {grp, grp+8}
    const int nw    = wid & 1;      // 0..1 : code cols nw*64..+63 within chunk

    const int n0  = blockIdx.x * M_TILE;
    const int bb  = n0 >> 12;
    const int hw0 = n0 & (HW - 1);
    const float* zb = z + (size_t)bb * CDIM * HW + hw0;

    // ---- issue cp.async for chunk 0 (hi + lo) ----
    // 2048 16B-items: item = tid + 256*t ; mat = item>>10, row = (item>>3)&127, part = item&7
    {
        #pragma unroll
        for (int t = 0; t < 8; t++) {
            int item = tid + 256 * t;
            int mat  = item >> 10;
            int row  = (item >> 3) & 127;
            int part = item & 7;
            const __half* src = (mat ? g_embl : g_embh) + row * 64 + part * 8;
            uint32_t dst = sb + (mat ? OFF_BL0 : OFF_BH0) + row * B_STRIDE + part * 16;
            cp16(dst, src);
        }
        cp_commit();
    }

    // ---- stage z (scaled) ----
    #pragma unroll
    for (int t = 0; t < 16; t++) {
        int i = tid + 256 * t;
        int c = i >> 6, tok = i & 63;
        zs[c * 68 + tok] = zb[(size_t)c * HW + tok] * SCALE;
    }
    // ---- esq (pre-scaled in prep) ----
    #pragma unroll
    for (int j = 0; j < 16; j++)
        esq_s[tid + j * 256] = g_esq[tid + j * 256];
    __syncthreads();

    // ---- A fragments (hi + lo) in registers: warp tile m16 ----
    uint32_t Ah[4][4], Al[4][4];
    {
        const int r0 = mwarp * 16 + grp;
        #pragma unroll
        for (int s = 0; s < 4; s++) {
            const int kb = 2 * tid4 + 16 * s;
            #pragma unroll
            for (int j = 0; j < 4; j++) {
                const int kk = kb + (j >> 1) * 8;
                const int rr = r0 + (j & 1) * 8;
                float v0 = zs[kk * 68 + rr];
                float v1 = zs[(kk + 1) * 68 + rr];
                __half h0 = __float2half_rn(v0), h1 = __float2half_rn(v1);
                Ah[s][j] = (uint32_t)__half_as_ushort(h0) | ((uint32_t)__half_as_ushort(h1) << 16);
                Al[s][j] = pack2h(v0 - __half2float(h0), v1 - __half2float(h1));
            }
        }
    }
    cp_wait<0>();
    __syncthreads();

    const int lrow  = (lane & 7) + ((lane >> 4) & 1) * 8;
    const int lkoff = ((lane >> 3) & 1) * 16;
    const uint32_t bladdr = (uint32_t)(nw * 64 + lrow) * B_STRIDE + lkoff;
    const uint32_t bh_off[2] = { OFF_BH0, OFF_BH1 };
    const uint32_t bl_off[2] = { OFF_BL0, OFF_BL1 };

    float best[2];
    int   bidx[2];
    best[0] = best[1] = FLT_MAX;
    bidx[0] = bidx[1] = 0;

    for (int ch = 0; ch < NCHUNKS; ch++) {
        const int buf = ch & 1;

        // issue next chunk into buf^1
        if (ch < NCHUNKS - 1) {
            const size_t cbase = (size_t)(ch + 1) * N_CHUNK * CDIM;
            #pragma unroll
            for (int t = 0; t < 8; t++) {
                int item = tid + 256 * t;
                int mat  = item >> 10;
                int row  = (item >> 3) & 127;
                int part = item & 7;
                const __half* src = (mat ? g_embl : g_embh) + cbase + row * 64 + part * 8;
                uint32_t dst = sb + (mat ? bl_off[buf ^ 1] : bh_off[buf ^ 1]) + row * B_STRIDE + part * 16;
                cp16(dst, src);
            }
            cp_commit();
        }

        float acc[8][4];
        #pragma unroll
        for (int f = 0; f < 8; f++)
            #pragma unroll
            for (int r = 0; r < 4; r++) acc[f][r] = 0.f;

        const uint32_t bhb = sb + bh_off[buf] + bladdr;
        const uint32_t blb = sb + bl_off[buf] + bladdr;
        #pragma unroll
        for (int s = 0; s < 4; s++) {
            #pragma unroll
            for (int fp = 0; fp < 4; fp++) {
                uint32_t h0, h1, h2, h3, L0, L1, L2, L3;
                ldmx4(h0, h1, h2, h3, bhb + fp * (16 * B_STRIDE) + s * 32);
                ldmx4(L0, L1, L2, L3, blb + fp * (16 * B_STRIDE) + s * 32);
                const int f0 = 2 * fp, f1 = 2 * fp + 1;
                mma16816(acc[f0], Ah[s], h0, h1);   // hi*hi
                mma16816(acc[f1], Ah[s], h2, h3);
                mma16816(acc[f0], Ah[s], L0, L1);   // hi*lo
                mma16816(acc[f1], Ah[s], L2, L3);
                mma16816(acc[f0], Al[s], h0, h1);   // lo*hi
                mma16816(acc[f1], Al[s], h2, h3);
            }
        }

        // ---- epilogue: min-tree + rare rescan (exact, first-min tiebreak) ----
        const int cb = ch * N_CHUNK + nw * 64;
        float2 ee[8];
        #pragma unroll
        for (int f = 0; f < 8; f++)
            ee[f] = *(const float2*)&esq_s[cb + f * 8 + 2 * tid4];

        #pragma unroll
        for (int g = 0; g < 2; g++) {   // g=0 -> row grp (c0,c1); g=1 -> row grp+8 (c2,c3)
            float sv[16];
            #pragma unroll
            for (int f = 0; f < 8; f++) {
                sv[2 * f]     = fmaf(acc[f][g * 2 + 0], -2.0f, ee[f].x);
                sv[2 * f + 1] = fmaf(acc[f][g * 2 + 1], -2.0f, ee[f].y);
            }
            float mn = sv[0];
            #pragma unroll
            for (int j = 1; j < 16; j++) mn = fminf(mn, sv[j]);
            if (mn < best[g]) {
                best[g] = mn;
                int found = -1;
                #pragma unroll
                for (int j = 0; j < 16; j++)
                    if (found < 0 && sv[j] == mn)
                        found = cb + (j >> 1) * 8 + 2 * tid4 + (j & 1);
                bidx[g] = found;
            }
        }

        cp_wait<0>();
        __syncthreads();
    }

    // ---- reduce over tid4 quad (codes), then over nw via smem ----
    #pragma unroll
    for (int g = 0; g < 2; g++) {
        float v  = best[g];
        int   id = bidx[g];
        #pragma unroll
        for (int off = 1; off <= 2; off <<= 1) {
            float ov = __shfl_xor_sync(0xffffffffu, v, off);
            int   oi = __shfl_xor_sync(0xffffffffu, id, off);
            if (ov < v || (ov == v && oi < id)) { v = ov; id = oi; }
        }
        if (tid4 == 0) {
            int token = mwarp * 16 + g * 8 + grp;
            candv[nw * 64 + token] = v;
            candi[nw * 64 + token] = id;
        }
    }
    __syncthreads();
    if (tid < 64) {
        float v0 = candv[tid], v1 = candv[64 + tid];
        int   i0 = candi[tid], i1 = candi[64 + tid];
        sidx[tid] = (v1 < v0 || (v1 == v0 && i1 < i0)) ? i1 : i0;
    }
    __syncthreads();

    // ---- gather emb[idx], transposed coalesced write (stage in zs region) ----
    float* st = zs;   // [64][65]
    #pragma unroll
    for (int t = 0; t < 16; t++) {
        int i = tid + 256 * t;
        int tok = i >> 6, c = i & 63;
        st[tok * 65 + c] = emb[(size_t)sidx[tok] * CDIM + c];
    }
    __syncthreads();
    float* ob = out + (size_t)bb * CDIM * HW + hw0;
    #pragma unroll
    for (int t = 0; t < 16; t++) {
        int i = tid + 256 * t;
        int c = i >> 6, tok = i & 63;
        ob[(size_t)c * HW + tok] = st[tok * 65 + c];
    }
}

extern "C" void kernel_launch(void* const* d_in, const int* in_sizes, int n_in,
                              void* d_out, int out_size) {
    const float* z   = (const float*)d_in[0];
    const float* emb = (const float*)d_in[1];
    float* out = (float*)d_out;

    cudaFuncSetAttribute(vq_kernel, cudaFuncAttributeMaxDynamicSharedMemorySize, SMEM_TOTAL);

    prep_kernel<<<NCODES / 8, 256>>>(emb);
    vq_kernel<<<NTOK / M_TILE, THREADS, SMEM_TOTAL>>>(z, emb, out);
}